// round 9
// baseline (speedup 1.0000x reference)
#include <cuda_runtime.h>
#include <cuda_bf16.h>
#include <math.h>
#include <stdint.h>

#define BB 2048
#define TT 80
#define LL 128
#define MT 8              // batch rows per CTA (padded to 16 in the MMA tile)
#define NCF 256           // grid: 2 CTAs per SM
#define SVS 136           // padded V row stride in bf16 elems

// ---- helpers ----
__device__ __forceinline__ uint32_t packbf2(float lo, float hi) {
    uint32_t r;
    asm("cvt.rn.satfinite.bf16x2.f32 %0, %1, %2;" : "=r"(r) : "f"(hi), "f"(lo));
    return r;
}
__device__ __forceinline__ uint32_t smem_u32(const void* p) {
    uint32_t a;
    asm("{ .reg .u64 t; cvta.to.shared.u64 t, %1; cvt.u32.u64 %0, t; }" : "=r"(a) : "l"(p));
    return a;
}
__device__ __forceinline__ void ldsm4(uint32_t r[4], uint32_t addr) {
    asm volatile("ldmatrix.sync.aligned.m8n8.x4.shared.b16 {%0,%1,%2,%3}, [%4];"
        : "=r"(r[0]), "=r"(r[1]), "=r"(r[2]), "=r"(r[3]) : "r"(addr));
}
__device__ __forceinline__ void mma16816(float d[4], const uint32_t a[4], const uint32_t b[2]) {
    asm volatile("mma.sync.aligned.m16n8k16.row.col.f32.bf16.bf16.f32 "
        "{%0,%1,%2,%3}, {%4,%5,%6,%7}, {%8,%9}, {%0,%1,%2,%3};"
        : "+f"(d[0]), "+f"(d[1]), "+f"(d[2]), "+f"(d[3])
        : "r"(a[0]), "r"(a[1]), "r"(a[2]), "r"(a[3]), "r"(b[0]), "r"(b[1]));
}

// -------------------------------------------------------------------------
// Fused CRF kernel. 256 CTAs x 256 thr (8 warps) -> 2 CTAs/SM, two
// independent recursion chains per SM. Each CTA owns 8 batch rows,
// padded to an m16 MMA tile (rows 8-15 zero, results discarded).
// Warp w owns n-slice [16w,16w+16). B = exp(trans) in regs.
// Emissions: direct per-lane LDG at fragment coords, 2 steps ahead.
// Renorm every 8 steps. Numerator fused at kernel start.
// -------------------------------------------------------------------------
__global__ void __launch_bounds__(256, 2) crf_fwd_kernel(
    const float* __restrict__ x,
    const float* __restrict__ trans,
    const float* __restrict__ st,
    const float* __restrict__ et,
    const int*   __restrict__ y,
    float*       __restrict__ out)
{
    __shared__ __align__(16) __nv_bfloat16 sV[2][16 * SVS];  // 16 rows (8 pad)
    __shared__ float sSt[LL];
    __shared__ float sRed[8][MT];
    __shared__ float sS[MT];
    __shared__ float sNum[MT][32];

    const int tid  = threadIdx.x;
    const int w    = tid >> 5;
    const int lane = tid & 31;
    const int gb   = blockIdx.x * MT;

    // ---- static B fragments: exp(trans)[k][n] in mma col-B layout ----
    uint32_t Bf[8][2][2];
    {
        const int jn = 16 * w + (lane >> 2);
        const int kb = (lane & 3) * 2;
        #pragma unroll
        for (int ks = 0; ks < 8; ks++)
            #pragma unroll
            for (int nt = 0; nt < 2; nt++) {
                int j  = jn + nt * 8;
                int k0 = ks * 16 + kb;
                Bf[ks][nt][0] = packbf2(__expf(trans[k0 * LL + j]),
                                        __expf(trans[(k0 + 1) * LL + j]));
                Bf[ks][nt][1] = packbf2(__expf(trans[(k0 + 8) * LL + j]),
                                        __expf(trans[(k0 + 9) * LL + j]));
            }
    }
    const int rQ  = lane >> 2;          // 0..7 = my batch row (h = 0 half)
    const int cQ2 = (lane & 3) * 2;
    const int c0  = 16 * w + cQ2;
    float eet[2][2];
    eet[0][0] = __expf(et[c0]);     eet[0][1] = __expf(et[c0 + 1]);
    eet[1][0] = __expf(et[c0 + 8]); eet[1][1] = __expf(et[c0 + 9]);
    if (tid < LL) sSt[tid] = st[tid];
    if (tid < MT) sS[tid] = 0.0f;

    // ---- gold-path numerator: 32 threads per row ----
    {
        const int nrow = tid >> 5, nsub = tid & 31;
        const int*   yr = y + (gb + nrow) * TT;
        const float* xn = x + (size_t)(gb + nrow) * TT * LL;
        float nacc = 0.0f;
        {
            int t = nsub;
            int cur = yr[t];
            nacc += xn[t * LL + cur] + trans[cur * LL + yr[t + 1]];
        }
        {
            int t = nsub + 32;
            int cur = yr[t];
            nacc += xn[t * LL + cur] + trans[cur * LL + yr[t + 1]];
        }
        if (nsub < 16) {
            int t = nsub + 64;
            int cur = yr[t];
            nacc += xn[t * LL + cur];
            if (t < TT - 1) nacc += trans[cur * LL + yr[t + 1]];
        }
        if (nsub == 0) nacc += st[yr[0]] + et[yr[TT - 1]];
        sNum[nrow][nsub] = nacc;
    }
    __syncthreads();

    // ---- t = 0 init: rows 0-7 = exp(st + x0); rows 8-15 = 0 (both buffers) ----
    {
        const int prow = tid >> 4;          // 0..15
        const int pc   = (tid & 15) * 8;
        if (prow < MT) {
            const float* xr = x + ((size_t)(gb + prow) * TT) * LL + pc;
            float4 a = *(const float4*)(xr);
            float4 b = *(const float4*)(xr + 4);
            uint4 v;
            v.x = packbf2(__expf(sSt[pc + 0] + a.x), __expf(sSt[pc + 1] + a.y));
            v.y = packbf2(__expf(sSt[pc + 2] + a.z), __expf(sSt[pc + 3] + a.w));
            v.z = packbf2(__expf(sSt[pc + 4] + b.x), __expf(sSt[pc + 5] + b.y));
            v.w = packbf2(__expf(sSt[pc + 6] + b.z), __expf(sSt[pc + 7] + b.w));
            *(uint4*)&sV[0][prow * SVS + pc] = v;
            *(uint4*)&sV[1][prow * SVS + pc] = make_uint4(0, 0, 0, 0);
        } else {
            *(uint4*)&sV[0][prow * SVS + pc] = make_uint4(0, 0, 0, 0);
            *(uint4*)&sV[1][prow * SVS + pc] = make_uint4(0, 0, 0, 0);
        }
    }

    // ---- emission prefetch (row rQ only; 2 steps ahead) ----
    const float* xrA = x + ((size_t)(gb + rQ) * TT) * LL + c0;
    float2 xpf[2][2];   // [t&1][nt]
    #pragma unroll
    for (int nt = 0; nt < 2; nt++) {
        xpf[1][nt] = *(const float2*)(xrA + LL + nt * 8);
        xpf[0][nt] = *(const float2*)(xrA + 2 * LL + nt * 8);
    }

    // ---- per-lane ldmatrix / STS offsets (bytes) ----
    const int rowL = lane & 15;
    const int sel8 = (lane >> 4) * 8;
    const uint32_t Aoff = (rowL * SVS + sel8) * 2;
    const uint32_t Voff = (rQ * SVS + 16 * w + cQ2) * 2;   // rows 0-7 only

    const uint32_t svb[2] = { smem_u32(&sV[0][0]), smem_u32(&sV[1][0]) };

    float val[2][2];   // [nt][col pair]

    for (int t = 1; t < TT; t++) {
        const int rd = (t - 1) & 1, wr = t & 1;
        __syncthreads();

        // A fragments (16 rows: 8 live + 8 zero)
        uint32_t Af[8][4];
        #pragma unroll
        for (int ks = 0; ks < 8; ks++)
            ldsm4(Af[ks], svb[rd] + Aoff + ks * 32);

        // emissions for this step
        float P[2][2];
        #pragma unroll
        for (int nt = 0; nt < 2; nt++) {
            float2 xv = xpf[wr][nt];
            P[nt][0] = __expf(xv.x);
            P[nt][1] = __expf(xv.y);
        }
        // refill for t+2
        if (t + 2 < TT) {
            #pragma unroll
            for (int nt = 0; nt < 2; nt++)
                xpf[wr][nt] = *(const float2*)(xrA + (size_t)(t + 2) * LL + nt * 8);
        }

        // split-K GEMM (rows 8-15 of D are pad, ignored)
        float D0[2][4] = {{0.f,0.f,0.f,0.f},{0.f,0.f,0.f,0.f}};
        float D1[2][4] = {{0.f,0.f,0.f,0.f},{0.f,0.f,0.f,0.f}};
        #pragma unroll
        for (int ks = 0; ks < 4; ks++) {
            mma16816(D0[0], Af[ks],     Bf[ks][0]);
            mma16816(D0[1], Af[ks],     Bf[ks][1]);
            mma16816(D1[0], Af[ks + 4], Bf[ks + 4][0]);
            mma16816(D1[1], Af[ks + 4], Bf[ks + 4][1]);
        }
        #pragma unroll
        for (int nt = 0; nt < 2; nt++) {
            val[nt][0] = (D0[nt][0] + D1[nt][0]) * P[nt][0];
            val[nt][1] = (D0[nt][1] + D1[nt][1]) * P[nt][1];
        }

        // per-row renorm every 8 steps
        if ((t & 7) == 0) {
            float m = fmaxf(fmaxf(val[0][0], val[0][1]),
                            fmaxf(val[1][0], val[1][1]));
            m = fmaxf(m, __shfl_xor_sync(0xffffffffu, m, 1));
            m = fmaxf(m, __shfl_xor_sync(0xffffffffu, m, 2));
            if ((lane & 3) == 0) sRed[w][rQ] = m;
            __syncthreads();
            float mm = sRed[0][rQ];
            #pragma unroll
            for (int w2 = 1; w2 < 8; w2++) mm = fmaxf(mm, sRed[w2][rQ]);
            float inv = 1.0f / mm;
            val[0][0] *= inv; val[0][1] *= inv;
            val[1][0] *= inv; val[1][1] *= inv;
            if (w == 0 && (lane & 3) == 0) sS[rQ] += logf(mm);
        }

        if (t < TT - 1) {
            char* vb = (char*)&sV[wr][0];
            *(uint32_t*)(vb + Voff)      = packbf2(val[0][0], val[0][1]);
            *(uint32_t*)(vb + Voff + 16) = packbf2(val[1][0], val[1][1]);
        }
    }

    // ---- epilogue: Z per row ----
    {
        float z = val[0][0] * eet[0][0] + val[0][1] * eet[0][1]
                + val[1][0] * eet[1][0] + val[1][1] * eet[1][1];
        z += __shfl_xor_sync(0xffffffffu, z, 1);
        z += __shfl_xor_sync(0xffffffffu, z, 2);
        if ((lane & 3) == 0) sRed[w][rQ] = z;
    }
    __syncthreads();
    if (tid < MT) {
        float Z = 0.0f;
        #pragma unroll
        for (int w2 = 0; w2 < 8; w2++) Z += sRed[w2][tid];
        float num = 0.0f;
        #pragma unroll
        for (int k = 0; k < 32; k++) num += sNum[tid][k];
        out[gb + tid] = num - (sS[tid] + logf(Z));
    }
}

// -------------------------------------------------------------------------
extern "C" void kernel_launch(void* const* d_in, const int* in_sizes, int n_in,
                              void* d_out, int out_size)
{
    const float* x     = (const float*)d_in[0];
    const float* trans = (const float*)d_in[1];
    const float* st    = (const float*)d_in[2];
    const float* et    = (const float*)d_in[3];
    const int*   y     = (const int*)  d_in[4];
    float*       out   = (float*)d_out;

    crf_fwd_kernel<<<NCF, 256>>>(x, trans, st, et, y, out);
}

// round 10
// speedup vs baseline: 1.0511x; 1.0511x over previous
#include <cuda_runtime.h>
#include <cuda_bf16.h>
#include <math.h>
#include <stdint.h>

#define BB 2048
#define TT 80
#define LL 128
#define MT 16             // batch rows per CTA
#define NCF 128           // grid: 1 CTA/SM, no padding
#define NTH 512           // 16 warps; warp owns one 8-col n-tile
#define SVS 136           // padded V row stride in bf16 elems

// ---- helpers ----
__device__ __forceinline__ uint32_t packbf2(float lo, float hi) {
    uint32_t r;
    asm("cvt.rn.satfinite.bf16x2.f32 %0, %1, %2;" : "=r"(r) : "f"(hi), "f"(lo));
    return r;
}
__device__ __forceinline__ uint32_t smem_u32(const void* p) {
    uint32_t a;
    asm("{ .reg .u64 t; cvta.to.shared.u64 t, %1; cvt.u32.u64 %0, t; }" : "=r"(a) : "l"(p));
    return a;
}
__device__ __forceinline__ void ldsm4(uint32_t r[4], uint32_t addr) {
    asm volatile("ldmatrix.sync.aligned.m8n8.x4.shared.b16 {%0,%1,%2,%3}, [%4];"
        : "=r"(r[0]), "=r"(r[1]), "=r"(r[2]), "=r"(r[3]) : "r"(addr));
}
__device__ __forceinline__ void mma16816(float d[4], const uint32_t a[4], const uint32_t b[2]) {
    asm volatile("mma.sync.aligned.m16n8k16.row.col.f32.bf16.bf16.f32 "
        "{%0,%1,%2,%3}, {%4,%5,%6,%7}, {%8,%9}, {%0,%1,%2,%3};"
        : "+f"(d[0]), "+f"(d[1]), "+f"(d[2]), "+f"(d[3])
        : "r"(a[0]), "r"(a[1]), "r"(a[2]), "r"(a[3]), "r"(b[0]), "r"(b[1]));
}

// -------------------------------------------------------------------------
// Fused CRF kernel. 128 CTAs x 512 thr (16 warps), 1 CTA/SM.
// Warp w owns the single n-tile [8w, 8w+8). B = exp(trans) in regs (16).
// CTA owns 16 batch rows (full m16 tile, no padding). V double-buffered
// in SMEM via ldmatrix. Emissions: per-lane LDG at fragment coords,
// 2 steps ahead. Renorm every 8 steps. Numerator fused at start.
// -------------------------------------------------------------------------
__global__ void __launch_bounds__(NTH, 1) crf_fwd_kernel(
    const float* __restrict__ x,
    const float* __restrict__ trans,
    const float* __restrict__ st,
    const float* __restrict__ et,
    const int*   __restrict__ y,
    float*       __restrict__ out)
{
    __shared__ __align__(16) __nv_bfloat16 sV[2][MT * SVS];
    __shared__ float sSt[LL];
    __shared__ float sRed[16][MT];
    __shared__ float sS[MT];
    __shared__ float sNum[MT][32];

    const int tid  = threadIdx.x;
    const int w    = tid >> 5;          // 0..15
    const int lane = tid & 31;
    const int gb   = blockIdx.x * MT;

    // ---- static B fragments for ONE n-tile: exp(trans)[k][8w + ...] ----
    uint32_t Bf[8][2];
    {
        const int j  = 8 * w + (lane >> 2);
        const int kb = (lane & 3) * 2;
        #pragma unroll
        for (int ks = 0; ks < 8; ks++) {
            int k0 = ks * 16 + kb;
            Bf[ks][0] = packbf2(__expf(trans[k0 * LL + j]),
                                __expf(trans[(k0 + 1) * LL + j]));
            Bf[ks][1] = packbf2(__expf(trans[(k0 + 8) * LL + j]),
                                __expf(trans[(k0 + 9) * LL + j]));
        }
    }
    const int rQ  = lane >> 2;          // 0..7
    const int cQ2 = (lane & 3) * 2;
    const int c0  = 8 * w + cQ2;        // my 2 columns
    float eet[2];
    eet[0] = __expf(et[c0]);
    eet[1] = __expf(et[c0 + 1]);
    if (tid < LL) sSt[tid] = st[tid];
    if (tid < MT) sS[tid] = 0.0f;

    // ---- gold-path numerator: 32 threads per row ----
    {
        const int nrow = tid >> 5, nsub = tid & 31;
        const int*   yr = y + (gb + nrow) * TT;
        const float* xn = x + (size_t)(gb + nrow) * TT * LL;
        float nacc = 0.0f;
        {
            int cur = yr[nsub];
            nacc += xn[nsub * LL + cur] + trans[cur * LL + yr[nsub + 1]];
        }
        {
            int t = nsub + 32;
            int cur = yr[t];
            nacc += xn[t * LL + cur] + trans[cur * LL + yr[t + 1]];
        }
        if (nsub < 16) {
            int t = nsub + 64;
            int cur = yr[t];
            nacc += xn[t * LL + cur];
            if (t < TT - 1) nacc += trans[cur * LL + yr[t + 1]];
        }
        if (nsub == 0) nacc += st[yr[0]] + et[yr[TT - 1]];
        sNum[nrow][nsub] = nacc;
    }
    __syncthreads();

    // ---- t = 0 init: V0 = exp(st + x0); 32 thr/row x 4 cols ----
    {
        const int prow = tid >> 5;
        const int pc   = (tid & 31) * 4;
        const float* xr = x + ((size_t)(gb + prow) * TT) * LL + pc;
        float4 a = *(const float4*)(xr);
        uint2 v;
        v.x = packbf2(__expf(sSt[pc + 0] + a.x), __expf(sSt[pc + 1] + a.y));
        v.y = packbf2(__expf(sSt[pc + 2] + a.z), __expf(sSt[pc + 3] + a.w));
        *(uint2*)&sV[0][prow * SVS + pc] = v;
    }

    // ---- emission prefetch (rows rQ / rQ+8, my 2 cols; 2 steps ahead) ----
    const float* xrA = x + ((size_t)(gb + rQ)     * TT) * LL + c0;
    const float* xrB = x + ((size_t)(gb + rQ + 8) * TT) * LL + c0;
    float2 xpf[2][2];   // [t&1][A/B]
    xpf[1][0] = *(const float2*)(xrA + LL);
    xpf[1][1] = *(const float2*)(xrB + LL);
    xpf[0][0] = *(const float2*)(xrA + 2 * LL);
    xpf[0][1] = *(const float2*)(xrB + 2 * LL);

    // ---- per-lane ldmatrix / STS offsets (bytes) ----
    const int rowL = lane & 15;
    const int sel8 = (lane >> 4) * 8;
    const uint32_t Aoff = (rowL * SVS + sel8) * 2;
    uint32_t Voff[2];
    #pragma unroll
    for (int h = 0; h < 2; h++)
        Voff[h] = ((h * 8 + rQ) * SVS + 8 * w + cQ2) * 2;

    const uint32_t svb[2] = { smem_u32(&sV[0][0]), smem_u32(&sV[1][0]) };

    float val[4];   // rows {rQ, rQ+8} x cols {c0, c0+1}

    for (int t = 1; t < TT; t++) {
        const int rd = (t - 1) & 1, wr = t & 1;
        __syncthreads();

        // A fragments (all 8 k-tiles)
        uint32_t Af[8][4];
        #pragma unroll
        for (int ks = 0; ks < 8; ks++)
            ldsm4(Af[ks], svb[rd] + Aoff + ks * 32);

        // emissions for this step
        float P[4];
        {
            float2 xa = xpf[wr][0], xb = xpf[wr][1];
            P[0] = __expf(xa.x);  P[1] = __expf(xa.y);
            P[2] = __expf(xb.x);  P[3] = __expf(xb.y);
        }
        // refill for t+2
        if (t + 2 < TT) {
            xpf[wr][0] = *(const float2*)(xrA + (size_t)(t + 2) * LL);
            xpf[wr][1] = *(const float2*)(xrB + (size_t)(t + 2) * LL);
        }

        // split-K GEMM (one n-tile)
        float D0[4] = {0.f, 0.f, 0.f, 0.f};
        float D1[4] = {0.f, 0.f, 0.f, 0.f};
        #pragma unroll
        for (int ks = 0; ks < 4; ks++) {
            mma16816(D0, Af[ks],     Bf[ks]);
            mma16816(D1, Af[ks + 4], Bf[ks + 4]);
        }
        #pragma unroll
        for (int k = 0; k < 4; k++)
            val[k] = (D0[k] + D1[k]) * P[k];

        // per-row renorm every 8 steps
        if ((t & 7) == 0) {
            #pragma unroll
            for (int h = 0; h < 2; h++) {
                float m = fmaxf(val[2 * h], val[2 * h + 1]);
                m = fmaxf(m, __shfl_xor_sync(0xffffffffu, m, 1));
                m = fmaxf(m, __shfl_xor_sync(0xffffffffu, m, 2));
                if ((lane & 3) == 0) sRed[w][h * 8 + rQ] = m;
            }
            __syncthreads();
            #pragma unroll
            for (int h = 0; h < 2; h++) {
                int row = h * 8 + rQ;
                float m = sRed[0][row];
                #pragma unroll
                for (int w2 = 1; w2 < 16; w2++) m = fmaxf(m, sRed[w2][row]);
                float inv = 1.0f / m;
                val[2 * h] *= inv;
                val[2 * h + 1] *= inv;
                if (w == 0 && (lane & 3) == 0) sS[row] += logf(m);
            }
        }

        if (t < TT - 1) {
            char* vb = (char*)&sV[wr][0];
            *(uint32_t*)(vb + Voff[0]) = packbf2(val[0], val[1]);
            *(uint32_t*)(vb + Voff[1]) = packbf2(val[2], val[3]);
        }
    }

    // ---- epilogue: Z per row ----
    #pragma unroll
    for (int h = 0; h < 2; h++) {
        float z = val[2 * h] * eet[0] + val[2 * h + 1] * eet[1];
        z += __shfl_xor_sync(0xffffffffu, z, 1);
        z += __shfl_xor_sync(0xffffffffu, z, 2);
        if ((lane & 3) == 0) sRed[w][h * 8 + rQ] = z;
    }
    __syncthreads();
    if (tid < MT) {
        float Z = 0.0f;
        #pragma unroll
        for (int w2 = 0; w2 < 16; w2++) Z += sRed[w2][tid];
        float num = 0.0f;
        #pragma unroll
        for (int k = 0; k < 32; k++) num += sNum[tid][k];
        out[gb + tid] = num - (sS[tid] + logf(Z));
    }
}

// -------------------------------------------------------------------------
extern "C" void kernel_launch(void* const* d_in, const int* in_sizes, int n_in,
                              void* d_out, int out_size)
{
    const float* x     = (const float*)d_in[0];
    const float* trans = (const float*)d_in[1];
    const float* st    = (const float*)d_in[2];
    const float* et    = (const float*)d_in[3];
    const int*   y     = (const int*)  d_in[4];
    float*       out   = (float*)d_out;

    crf_fwd_kernel<<<NCF, NTH>>>(x, trans, st, et, y, out);
}